// round 1
// baseline (speedup 1.0000x reference)
#include <cuda_runtime.h>

#define THREADS 256
#define NWARP (THREADS / 32)
#define TOPK 5
#define NCAT 8
#define FULLM 0xffffffffu
#define L2E 1.4426950408889634f
#define LN2 0.6931471805599453f

// scratch: per-row weighted loss (B = 4096 here; capacity margin)
__device__ float g_rowloss[8192];

__device__ __forceinline__ float ex2f(float x) {
    float y; asm("ex2.approx.ftz.f32 %0, %1;" : "=f"(y) : "f"(x)); return y;
}
__device__ __forceinline__ float lg2f(float x) {
    float y; asm("lg2.approx.ftz.f32 %0, %1;" : "=f"(y) : "f"(x)); return y;
}

// sorted-descending insert of (v, idx), caller guarantees v > tv[TOPK-1]
__device__ __forceinline__ void insert5(float (&tv)[TOPK], int (&ti)[TOPK], float v, int idx) {
    tv[TOPK - 1] = v; ti[TOPK - 1] = idx;
#pragma unroll
    for (int k = TOPK - 1; k > 0; --k) {
        if (tv[k] > tv[k - 1]) {
            float tf = tv[k]; tv[k] = tv[k - 1]; tv[k - 1] = tf;
            int   tt = ti[k]; ti[k] = ti[k - 1]; ti[k - 1] = tt;
        }
    }
}

__global__ void __launch_bounds__(THREADS)
hier_loss_rows(const float* __restrict__ logits,
               const int* __restrict__ labels,
               const int* __restrict__ catlab,
               const int* __restrict__ c2c,
               int V, int ncmd)
{
    const int b    = blockIdx.x;
    const int tid  = threadIdx.x;
    const int lane = tid & 31;
    const int w    = tid >> 5;
    const float* row = logits + (size_t)b * (size_t)V;

    __shared__ int   s_c2c[64];
    __shared__ float s_wC[NWARP], s_wS[NWARP];
    __shared__ float s_wTv[NWARP][TOPK];
    __shared__ int   s_wTi[NWARP][TOPK];
    __shared__ float s_cat[NCAT];

    if (tid < 64 && tid < ncmd) s_c2c[tid] = c2c[tid];

    // warp-replicated top-5 (identical in all lanes of a warp)
    float tv[TOPK]; int ti[TOPK];
#pragma unroll
    for (int k = 0; k < TOPK; ++k) { tv[k] = -__int_as_float(0x7f800000); ti[k] = 0; }

    // per-thread log2-domain softmax accumulation with fixed base C
    float x0   = (tid < V) ? __ldg(row + tid) : 0.0f;
    float negC = -x0 * L2E;                 // C = x0 * log2(e)
    float s0 = 0.0f, s1 = 0.0f;
    float thr_d = -__int_as_float(0x7f800000);

    const int nIter = V / (4 * THREADS);
    const float* p  = row + tid;
    int ibase = 0;

    for (int j = 0; j < nIter; ++j) {
        float xa = __ldg(p);
        float xb = __ldg(p + THREADS);
        float xc = __ldg(p + 2 * THREADS);
        float xd = __ldg(p + 3 * THREADS);
        p += 4 * THREADS;

        float da = fmaf(xa, L2E, negC);
        float db = fmaf(xb, L2E, negC);
        float dc = fmaf(xc, L2E, negC);
        float dd = fmaf(xd, L2E, negC);
        s0 += ex2f(da); s1 += ex2f(db);
        s0 += ex2f(dc); s1 += ex2f(dd);

        float dm = fmaxf(fmaxf(da, db), fmaxf(dc, dd));

        // rare rebase to keep ex2 args bounded (never fires for N(0,1) data)
        if (dm > 60.0f) {
            float sc = ex2f(-dm);
            s0 *= sc; s1 *= sc;
            negC -= dm;
            thr_d = fmaf(tv[TOPK - 1], L2E, negC);
        }

        // warp-level top-5 candidate filter: dm > thr_d  <=>  max(x) > tv[4]
        unsigned bal = __ballot_sync(FULLM, dm > thr_d);
        if (bal) {
            float xq[4] = {xa, xb, xc, xd};
            while (bal) {
                int L = __ffs(bal) - 1; bal &= bal - 1;
#pragma unroll
                for (int q = 0; q < 4; ++q) {
                    float xv = __shfl_sync(FULLM, xq[q], L);
                    if (xv > tv[TOPK - 1]) {
                        int xi = ibase + q * THREADS + (w << 5) + L;
                        insert5(tv, ti, xv, xi);
                    }
                }
            }
            thr_d = fmaf(tv[TOPK - 1], L2E, negC);
        }
        ibase += 4 * THREADS;
    }

    // tail (uniform masked iterations)
    for (int i0 = nIter * 4 * THREADS; i0 < V; i0 += THREADS) {
        int i = i0 + tid;
        bool valid = (i < V);
        float x = valid ? __ldg(row + i) : -__int_as_float(0x7f800000);
        float d = fmaf(x, L2E, negC);       // -inf -> ex2 = 0
        s0 += ex2f(d);
        unsigned bal = __ballot_sync(FULLM, d > thr_d);
        while (bal) {
            int L = __ffs(bal) - 1; bal &= bal - 1;
            float xv = __shfl_sync(FULLM, x, L);
            if (xv > tv[TOPK - 1]) insert5(tv, ti, xv, i0 + (w << 5) + L);
        }
        thr_d = fmaf(tv[TOPK - 1], L2E, negC);
    }

    // warp-reduce (C, s) in log2 domain
    float s = s0 + s1;
    float C = -negC;
#pragma unroll
    for (int off = 16; off; off >>= 1) {
        float Co = __shfl_xor_sync(FULLM, C, off);
        float so = __shfl_xor_sync(FULLM, s, off);
        float Cn = fmaxf(C, Co);
        s = s * ex2f(C - Cn) + so * ex2f(Co - Cn);
        C = Cn;
    }

    if (lane == 0) {
        s_wC[w] = C; s_wS[w] = s;
#pragma unroll
        for (int k = 0; k < TOPK; ++k) { s_wTv[w][k] = tv[k]; s_wTi[w][k] = ti[k]; }
    }
    __syncthreads();

    if (tid == 0) {
        float Cf = s_wC[0], sf = s_wS[0];
        for (int ww = 1; ww < NWARP; ++ww) {
            float Co = s_wC[ww], so = s_wS[ww];
            float Cn = fmaxf(Cf, Co);
            sf = sf * ex2f(Cf - Cn) + so * ex2f(Co - Cn);
            Cf = Cn;
        }
        float ftv[TOPK]; int fti[TOPK];
#pragma unroll
        for (int k = 0; k < TOPK; ++k) { ftv[k] = s_wTv[0][k]; fti[k] = s_wTi[0][k]; }
        for (int ww = 1; ww < NWARP; ++ww) {
            for (int k = 0; k < TOPK; ++k) {
                float v = s_wTv[ww][k];
                if (v > ftv[TOPK - 1]) insert5(ftv, fti, v, s_wTi[ww][k]);
                else break;   // lists are sorted descending
            }
        }

        // command CE term for this row
        float lse  = (Cf + lg2f(sf)) * LN2;       // natural-log logsumexp
        int   lab  = __ldg(labels + b);
        float xlab = __ldg(row + lab);
        float nll_cmd = lse - xlab;

        // category logits: scatter top-5 into 8 bins (zeros participate)
#pragma unroll
        for (int c = 0; c < NCAT; ++c) s_cat[c] = 0.0f;
#pragma unroll
        for (int k = 0; k < TOPK; ++k)
            s_cat[s_c2c[fti[k] % ncmd]] += ftv[k];

        float mx = s_cat[0];
#pragma unroll
        for (int c = 1; c < NCAT; ++c) mx = fmaxf(mx, s_cat[c]);
        float ssum = 0.0f;
#pragma unroll
        for (int c = 0; c < NCAT; ++c) ssum += ex2f((s_cat[c] - mx) * L2E);
        int   cl = __ldg(catlab + b);
        float nll_cat = lg2f(ssum) * LN2 + mx - s_cat[cl];

        g_rowloss[b] = 0.6f * nll_cmd + 0.4f * nll_cat;
    }
}

__global__ void __launch_bounds__(256)
hier_loss_finalize(float* __restrict__ out, int B)
{
    __shared__ float sh[256];
    int tid = threadIdx.x;
    float a = 0.0f;
    for (int i = tid; i < B; i += 256) a += g_rowloss[i];
    sh[tid] = a;
    __syncthreads();
#pragma unroll
    for (int off = 128; off; off >>= 1) {
        if (tid < off) sh[tid] += sh[tid + off];
        __syncthreads();
    }
    if (tid == 0) out[0] = sh[0] * (1.0f / (float)B);
}

extern "C" void kernel_launch(void* const* d_in, const int* in_sizes, int n_in,
                              void* d_out, int out_size)
{
    const float* logits = (const float*)d_in[0];
    const int*   labels = (const int*)d_in[1];
    const int*   catlab = (const int*)d_in[2];
    const int*   c2c    = (const int*)d_in[3];

    const int B    = in_sizes[1];
    const int V    = in_sizes[0] / B;
    const int ncmd = in_sizes[3];

    hier_loss_rows<<<B, THREADS>>>(logits, labels, catlab, c2c, V, ncmd);
    hier_loss_finalize<<<1, 256>>>((float*)d_out, B);
}